// round 16
// baseline (speedup 1.0000x reference)
#include <cuda_runtime.h>
#include <cuda_fp16.h>
#include <math_constants.h>
#include <cstdint>

// Problem constants
#define NN   12288
#define DIM  128
#define HID  16
#define CLS  16

// Aggregation tiling
#define NSPLIT   6
#define COLS_PS  (NN / NSPLIT)     // 2048 columns per split
#define CHUNK    512               // columns staged per pass
#define ROWS_CTA 128               // 8 warps x 16 rows
// grid = (NN/ROWS_CTA) * NSPLIT = 96*6 = 576 CTAs = one full wave at occ 4

// smem strides (fp16 elements), bank-conflict-free (verified lane maps)
#define S_N 24     // natural layout Hs[j][hid], j-stride
#define S_T 520    // transposed layout HsT[hid][j], hid-stride

#define SQRT_LOG2E 1.2011224087864498f   // sqrt(log2(e))

// Device scratch (no cudaMalloc allowed)
__device__ __align__(16) float g_Wc[DIM * CLS];     // combined weight
__device__ __align__(16) float g_bc[CLS];           // combined bias
__device__ __align__(16) __half g_Hs[NN * HID];     // h * sqrt(log2e), fp16
__device__ __align__(16) float g_num[NN * CLS];     // numerators (scaled; atomic)
__device__ __align__(16) float g_den[NN];           // denominators (atomic)

// ---------------------------------------------------------------------------
// PTX helpers
// ---------------------------------------------------------------------------
__device__ __forceinline__ void mma_f16(float& d0, float& d1, float& d2, float& d3,
                                        uint32_t a0, uint32_t a1, uint32_t a2, uint32_t a3,
                                        uint32_t b0, uint32_t b1) {
    asm volatile(
        "mma.sync.aligned.m16n8k16.row.col.f32.f16.f16.f32 "
        "{%0,%1,%2,%3}, {%4,%5,%6,%7}, {%8,%9}, {%0,%1,%2,%3};"
        : "+f"(d0), "+f"(d1), "+f"(d2), "+f"(d3)
        : "r"(a0), "r"(a1), "r"(a2), "r"(a3), "r"(b0), "r"(b1));
}

// fp16-accumulator variant: D/C fragments are two packed f16x2 registers.
__device__ __forceinline__ void mma_f16acc(uint32_t& c0, uint32_t& c1,
                                           uint32_t a0, uint32_t a1, uint32_t a2, uint32_t a3,
                                           uint32_t b0, uint32_t b1) {
    asm volatile(
        "mma.sync.aligned.m16n8k16.row.col.f16.f16.f16.f16 "
        "{%0,%1}, {%2,%3,%4,%5}, {%6,%7}, {%0,%1};"
        : "+r"(c0), "+r"(c1)
        : "r"(a0), "r"(a1), "r"(a2), "r"(a3), "r"(b0), "r"(b1));
}

__device__ __forceinline__ __half2 u2h(uint32_t v) { return *reinterpret_cast<__half2*>(&v); }
__device__ __forceinline__ uint32_t h2u(__half2 v) { return *reinterpret_cast<uint32_t*>(&v); }

// masked exp on a packed fp16 pair via MUFU: e = (s > 0) ? 2^s : 0
__device__ __forceinline__ uint32_t masked_exp2h(uint32_t ps) {
    uint32_t pe;
    asm("ex2.approx.f16x2 %0, %1;" : "=r"(pe) : "r"(ps));
    const __half2 z2 = __half2(__ushort_as_half(0), __ushort_as_half(0));
    __half2 m = __hgt2(u2h(ps), z2);   // 1.0 / 0.0 per half
    return h2u(__hmul2(u2h(pe), m));
}

// masked exp on a packed fp16 pair via fma/alu pipes (no MUFU):
// s = n + f (n = round(s) via +1024 magic, |f| <= 0.5);
// 2^n from bits: (t & 0xF) * 1024 + 0x3C00;  2^f by deg-2 minimax.
// For s <= 0 the 2^n bits are garbage but finite (never inf/NaN, n<=15
// caps at 0x7800); the mask zeroes those lanes.
__device__ __forceinline__ uint32_t masked_exp2h_soft(uint32_t ps) {
    const __half2 h1024 = u2h(0x64006400u);         // 1024.0 x2
    const __half2 z2    = u2h(0u);
    __half2 s  = u2h(ps);
    __half2 t  = __hadd2(s, h1024);                 // 1024 + round(s)   (RN)
    __half2 nf = __hsub2(t, h1024);                 // n (exact)
    __half2 f  = __hsub2(s, nf);                    // frac, |f| <= 0.5 (exact)
    // p = a2*f^2 + a1*f + a0  (minimax for 2^f on [-0.5, 0.5], ripple ~0.2%)
    __half2 p  = __hfma2(f, u2h(0x33C433C4u), u2h(0x39A139A1u)); // a2=0.24264, a1=0.70355
    p = __hfma2(p, f, u2h(0x3C003C00u));            // +a0 = 1.0
    const uint32_t E = (h2u(t) & 0x000F000Fu) * 1024u + 0x3C003C00u;  // 2^n bits x2
    __half2 e = __hmul2(u2h(E), p);
    __half2 m = __hgt2(s, z2);
    return h2u(__hmul2(e, m));
}

// ---------------------------------------------------------------------------
// Kernel 0: combined linear weights (layers are purely linear: no activation).
// Wc = W1 @ W2 @ W3 ; bc = (b1 @ W2 + b2) @ W3 + b3.  One block, 128 threads.
// ---------------------------------------------------------------------------
__global__ void precompute_kernel(const float* __restrict__ W1, const float* __restrict__ b1,
                                  const float* __restrict__ W2, const float* __restrict__ b2,
                                  const float* __restrict__ W3, const float* __restrict__ b3) {
    __shared__ float sW2[HID * HID];
    __shared__ float sW3[HID * CLS];
    const int t = threadIdx.x;
    for (int i = t; i < HID * HID; i += 128) sW2[i] = W2[i];
    for (int i = t; i < HID * CLS; i += 128) sW3[i] = W3[i];
    __syncthreads();

    // thread k computes row k of Wc
    float v[HID];
#pragma unroll
    for (int j = 0; j < HID; j++) v[j] = 0.f;
#pragma unroll
    for (int p = 0; p < HID; p++) {
        const float w = W1[t * HID + p];
#pragma unroll
        for (int j = 0; j < HID; j++) v[j] = fmaf(w, sW2[p * HID + j], v[j]);
    }
    float w[CLS];
#pragma unroll
    for (int j = 0; j < CLS; j++) w[j] = 0.f;
#pragma unroll
    for (int p = 0; p < HID; p++) {
#pragma unroll
        for (int j = 0; j < CLS; j++) w[j] = fmaf(v[p], sW3[p * CLS + j], w[j]);
    }
#pragma unroll
    for (int j = 0; j < CLS; j++) g_Wc[t * CLS + j] = w[j];

    if (t == 0) {
        float u[HID];
#pragma unroll
        for (int j = 0; j < HID; j++) u[j] = b2[j];
#pragma unroll
        for (int p = 0; p < HID; p++)
#pragma unroll
            for (int j = 0; j < HID; j++) u[j] = fmaf(b1[p], sW2[p * HID + j], u[j]);
        float bb[CLS];
#pragma unroll
        for (int j = 0; j < CLS; j++) bb[j] = b3[j];
#pragma unroll
        for (int p = 0; p < HID; p++)
#pragma unroll
            for (int j = 0; j < CLS; j++) bb[j] = fmaf(u[p], sW3[p * CLS + j], bb[j]);
#pragma unroll
        for (int j = 0; j < CLS; j++) g_bc[j] = bb[j];
    }
}

// ---------------------------------------------------------------------------
// Kernel 1: h = x @ Wc + bc -> g_Hs = fp16(h * sqrt(log2e)).
// One thread per (row, class). ALSO zeroes the atomic accumulators g_num/g_den.
// ---------------------------------------------------------------------------
__global__ __launch_bounds__(256)
void mlp_gemm(const float* __restrict__ x) {
    __shared__ float sWc[DIM * CLS];   // 8 KB
    __shared__ float sbc[CLS];

    const int tid = threadIdx.x;
    const int gid = blockIdx.x * 256 + tid;
    g_num[gid] = 0.f;
    if (gid < NN) g_den[gid] = 0.f;
    {
        const float4* src = reinterpret_cast<const float4*>(g_Wc);
        float4* dst = reinterpret_cast<float4*>(sWc);
        dst[tid]       = src[tid];
        dst[tid + 256] = src[tid + 256];
        if (tid < CLS) sbc[tid] = g_bc[tid];
    }
    __syncthreads();

    const int row = blockIdx.x * 16 + (tid >> 4);
    const int j   = tid & 15;

    const float4* xr = reinterpret_cast<const float4*>(x + (size_t)row * DIM);
    float a0 = 0.f, a1 = 0.f, a2 = 0.f, a3 = 0.f;
#pragma unroll
    for (int k4 = 0; k4 < 32; k4++) {
        const float4 xv = __ldg(&xr[k4]);
        a0 = fmaf(xv.x, sWc[(4 * k4 + 0) * CLS + j], a0);
        a1 = fmaf(xv.y, sWc[(4 * k4 + 1) * CLS + j], a1);
        a2 = fmaf(xv.z, sWc[(4 * k4 + 2) * CLS + j], a2);
        a3 = fmaf(xv.w, sWc[(4 * k4 + 3) * CLS + j], a3);
    }
    const float h = (a0 + a1) + (a2 + a3) + sbc[j];

    g_Hs[(size_t)row * HID + j] = __float2half(h * SQRT_LOG2E);
}

// ---------------------------------------------------------------------------
// Kernel 2: fused masked-softmax aggregation on tensor cores (fp16).
// Hybrid exp: 2 packed pairs on MUFU (ex2), 2 on the fma/alu pipes
// (integer-bit 2^n * deg-2 poly) — balances MUFU(32) vs issue(~48) per kc.
// ---------------------------------------------------------------------------
__global__ __launch_bounds__(256, 4)
void agg_kernel() {
    __shared__ __align__(16) __half sHn[CHUNK * S_N];  // Hs[j][hid]     (24.0 KB)
    __shared__ __align__(16) __half sHt[HID * S_T];    // Hs^T[hid][j]   (16.3 KB)

    const int tid  = threadIdx.x;
    const int lane = tid & 31;
    const int wid  = tid >> 5;        // 0..7
    const int g    = lane >> 2;       // 0..7
    const int t4   = lane & 3;        // 0..3

    const int split = blockIdx.y;
    const int rbase = blockIdx.x * ROWS_CTA + wid * 16;
    const int rg  = rbase + g;
    const int rg8 = rg + 8;

    // A-fragment: scaled rows (loop-invariant)
    uint32_t a0 = *reinterpret_cast<const uint32_t*>(g_Hs + (size_t)rg  * HID + 2 * t4);
    uint32_t a1 = *reinterpret_cast<const uint32_t*>(g_Hs + (size_t)rg8 * HID + 2 * t4);
    uint32_t a2 = *reinterpret_cast<const uint32_t*>(g_Hs + (size_t)rg  * HID + 2 * t4 + 8);
    uint32_t a3 = *reinterpret_cast<const uint32_t*>(g_Hs + (size_t)rg8 * HID + 2 * t4 + 8);

    float o00 = 0.f, o01 = 0.f, o02 = 0.f, o03 = 0.f;
    float o10 = 0.f, o11 = 0.f, o12 = 0.f, o13 = 0.f;
    __half2 dga = __half2(__ushort_as_half(0), __ushort_as_half(0));
    __half2 dgb = dga;

    const int j0 = split * COLS_PS;

    for (int cc = 0; cc < COLS_PS; cc += CHUNK) {
        __syncthreads();
#pragma unroll
        for (int it = 0; it < CHUNK / 256; it++) {
            const int j = tid + it * 256;
            const size_t gidx = (size_t)(j0 + cc + j) * HID;
            const uint4 vs0 = *reinterpret_cast<const uint4*>(g_Hs + gidx);
            const uint4 vs1 = *reinterpret_cast<const uint4*>(g_Hs + gidx + 8);
            *reinterpret_cast<uint4*>(&sHn[j * S_N])     = vs0;
            *reinterpret_cast<uint4*>(&sHn[j * S_N + 8]) = vs1;

            const uint32_t u[8] = {vs0.x, vs0.y, vs0.z, vs0.w, vs1.x, vs1.y, vs1.z, vs1.w};
#pragma unroll
            for (int w = 0; w < 8; w++) {
                __half2 bp = u2h(u[w]);
                sHt[(2 * w)     * S_T + j] = bp.x;
                sHt[(2 * w + 1) * S_T + j] = bp.y;
            }
        }
        __syncthreads();

#pragma unroll 16
        for (int kc = 0; kc < CHUNK / 16; kc++) {
            const int ja = 16 * kc + g;
            const int jb = ja + 8;
            uint32_t b0a = *reinterpret_cast<const uint32_t*>(&sHn[ja * S_N + 2 * t4]);
            uint32_t b1a = *reinterpret_cast<const uint32_t*>(&sHn[ja * S_N + 2 * t4 + 8]);
            uint32_t b0b = *reinterpret_cast<const uint32_t*>(&sHn[jb * S_N + 2 * t4]);
            uint32_t b1b = *reinterpret_cast<const uint32_t*>(&sHn[jb * S_N + 2 * t4 + 8]);

            uint32_t c0a = 0u, c1a = 0u, c0b = 0u, c1b = 0u;
            mma_f16acc(c0a, c1a, a0, a1, a2, a3, b0a, b1a);
            mma_f16acc(c0b, c1b, a0, a1, a2, a3, b0b, b1b);

            // hybrid masked exp: n-tile a on MUFU, n-tile b on fma/alu
            uint32_t pa0 = masked_exp2h(c0a);
            uint32_t pa1 = masked_exp2h(c1a);
            uint32_t pa2 = masked_exp2h_soft(c0b);
            uint32_t pa3 = masked_exp2h_soft(c1b);

            dga = __hadd2(dga, __hadd2(u2h(pa0), u2h(pa2)));
            dgb = __hadd2(dgb, __hadd2(u2h(pa1), u2h(pa3)));

            uint32_t q0n0 = *reinterpret_cast<const uint32_t*>(&sHt[g * S_T + 16 * kc + 2 * t4]);
            uint32_t q1n0 = *reinterpret_cast<const uint32_t*>(&sHt[g * S_T + 16 * kc + 2 * t4 + 8]);
            uint32_t q0n1 = *reinterpret_cast<const uint32_t*>(&sHt[(g + 8) * S_T + 16 * kc + 2 * t4]);
            uint32_t q1n1 = *reinterpret_cast<const uint32_t*>(&sHt[(g + 8) * S_T + 16 * kc + 2 * t4 + 8]);

            mma_f16(o00, o01, o02, o03, pa0, pa1, pa2, pa3, q0n0, q1n0);
            mma_f16(o10, o11, o12, o13, pa0, pa1, pa2, pa3, q0n1, q1n1);
        }
    }

    // den: unpack, reduce across the 4 lanes sharing each row
    float den_g  = __half2float(dga.x) + __half2float(dga.y);
    float den_g8 = __half2float(dgb.x) + __half2float(dgb.y);
    den_g  += __shfl_xor_sync(0xffffffffu, den_g, 1);
    den_g  += __shfl_xor_sync(0xffffffffu, den_g, 2);
    den_g8 += __shfl_xor_sync(0xffffffffu, den_g8, 1);
    den_g8 += __shfl_xor_sync(0xffffffffu, den_g8, 2);

    // epilogue: atomic accumulation (spread addresses; 6 colliders each)
    float* pn  = g_num + (size_t)rg  * CLS;
    float* pn8 = g_num + (size_t)rg8 * CLS;
    atomicAdd(&pn [2 * t4],     o00);  atomicAdd(&pn [2 * t4 + 1], o01);
    atomicAdd(&pn [2 * t4 + 8], o10);  atomicAdd(&pn [2 * t4 + 9], o11);
    atomicAdd(&pn8[2 * t4],     o02);  atomicAdd(&pn8[2 * t4 + 1], o03);
    atomicAdd(&pn8[2 * t4 + 8], o12);  atomicAdd(&pn8[2 * t4 + 9], o13);
    if (t4 == 0) {
        atomicAdd(&g_den[rg],  den_g);
        atomicAdd(&g_den[rg8], den_g8);
    }
}

// ---------------------------------------------------------------------------
// Kernel 3: out = num/(den*sqrt(log2e)), then row log-softmax.
// Single-pass gather; 16 threads per row.
// ---------------------------------------------------------------------------
__global__ __launch_bounds__(256)
void finalize_kernel(float* __restrict__ out) {
    const int idx = blockIdx.x * 256 + threadIdx.x;
    const int row = idx >> 4;
    const int c   = idx & 15;

    const float n   = g_num[(size_t)row * CLS + c];
    const float den = g_den[row];

    const float o = n / (den * SQRT_LOG2E);

    float m = o;
    m = fmaxf(m, __shfl_xor_sync(0xffffffffu, m, 1));
    m = fmaxf(m, __shfl_xor_sync(0xffffffffu, m, 2));
    m = fmaxf(m, __shfl_xor_sync(0xffffffffu, m, 4));
    m = fmaxf(m, __shfl_xor_sync(0xffffffffu, m, 8));

    float sum = expf(o - m);
    sum += __shfl_xor_sync(0xffffffffu, sum, 1);
    sum += __shfl_xor_sync(0xffffffffu, sum, 2);
    sum += __shfl_xor_sync(0xffffffffu, sum, 4);
    sum += __shfl_xor_sync(0xffffffffu, sum, 8);

    out[(size_t)row * CLS + c] = o - (logf(sum) + m);
}

// ---------------------------------------------------------------------------
extern "C" void kernel_launch(void* const* d_in, const int* in_sizes, int n_in,
                              void* d_out, int out_size) {
    const float* x  = (const float*)d_in[0];
    const float* W1 = (const float*)d_in[1];
    const float* b1 = (const float*)d_in[2];
    const float* W2 = (const float*)d_in[3];
    const float* b2 = (const float*)d_in[4];
    const float* W3 = (const float*)d_in[5];
    const float* b3 = (const float*)d_in[6];
    float* out = (float*)d_out;

    precompute_kernel<<<1, 128>>>(W1, b1, W2, b2, W3, b3);
    mlp_gemm<<<NN / 16, 256>>>(x);

    dim3 grid(NN / ROWS_CTA, NSPLIT);
    agg_kernel<<<grid, 256>>>();

    finalize_kernel<<<(NN * 16) / 256, 256>>>(out);
}

// round 17
// speedup vs baseline: 1.1903x; 1.1903x over previous
#include <cuda_runtime.h>
#include <cuda_fp16.h>
#include <math_constants.h>
#include <cstdint>

// Problem constants
#define NN   12288
#define DIM  128
#define HID  16
#define CLS  16

// Aggregation tiling
#define NSPLIT   6
#define COLS_PS  (NN / NSPLIT)     // 2048 columns per split
#define CHUNK    512               // columns staged per pass
#define ROWS_CTA 128               // 8 warps x 16 rows
// grid = (NN/ROWS_CTA) * NSPLIT = 96*6 = 576 CTAs = one full wave at occ 4

// smem stride (fp16 elements), bank-conflict-free
#define S_N 24     // natural layout Hs[j][hid], j-stride

#define SQRT_LOG2E 1.2011224087864498f   // sqrt(log2(e))

// Device scratch (no cudaMalloc allowed)
__device__ __align__(16) float g_Wc[DIM * CLS];     // combined weight
__device__ __align__(16) float g_bc[CLS];           // combined bias
__device__ __align__(16) __half g_Hs[NN * HID];     // h * sqrt(log2e), fp16
__device__ __align__(16) float g_num[NN * CLS];     // numerators (scaled; atomic)
__device__ __align__(16) float g_den[NN];           // denominators (atomic)

// ---------------------------------------------------------------------------
// PTX helpers
// ---------------------------------------------------------------------------
__device__ __forceinline__ void mma_f16(float& d0, float& d1, float& d2, float& d3,
                                        uint32_t a0, uint32_t a1, uint32_t a2, uint32_t a3,
                                        uint32_t b0, uint32_t b1) {
    asm volatile(
        "mma.sync.aligned.m16n8k16.row.col.f32.f16.f16.f32 "
        "{%0,%1,%2,%3}, {%4,%5,%6,%7}, {%8,%9}, {%0,%1,%2,%3};"
        : "+f"(d0), "+f"(d1), "+f"(d2), "+f"(d3)
        : "r"(a0), "r"(a1), "r"(a2), "r"(a3), "r"(b0), "r"(b1));
}

// fp16-accumulator variant: D/C fragments are two packed f16x2 registers.
__device__ __forceinline__ void mma_f16acc(uint32_t& c0, uint32_t& c1,
                                           uint32_t a0, uint32_t a1, uint32_t a2, uint32_t a3,
                                           uint32_t b0, uint32_t b1) {
    asm volatile(
        "mma.sync.aligned.m16n8k16.row.col.f16.f16.f16.f16 "
        "{%0,%1}, {%2,%3,%4,%5}, {%6,%7}, {%0,%1};"
        : "+r"(c0), "+r"(c1)
        : "r"(a0), "r"(a1), "r"(a2), "r"(a3), "r"(b0), "r"(b1));
}

// warp-collective 8x8 b16 transpose: lane(g,t4) in -> holds M[g][2t4..];
// out -> holds M[2t4][g], M[2t4+1][g] (exactly the col-major B-frag layout).
__device__ __forceinline__ uint32_t movm_t(uint32_t a) {
    uint32_t d;
    asm volatile("movmatrix.sync.aligned.m8n8.trans.b16 %0, %1;" : "=r"(d) : "r"(a));
    return d;
}

__device__ __forceinline__ __half2 u2h(uint32_t v) { return *reinterpret_cast<__half2*>(&v); }
__device__ __forceinline__ uint32_t h2u(__half2 v) { return *reinterpret_cast<uint32_t*>(&v); }

// masked exp on a packed fp16 pair via MUFU: e = (s > 0) ? 2^s : 0
__device__ __forceinline__ uint32_t masked_exp2h(uint32_t ps) {
    uint32_t pe;
    asm("ex2.approx.f16x2 %0, %1;" : "=r"(pe) : "r"(ps));
    const __half2 z2 = __half2(__ushort_as_half(0), __ushort_as_half(0));
    __half2 m = __hgt2(u2h(ps), z2);   // 1.0 / 0.0 per half
    return h2u(__hmul2(u2h(pe), m));
}

// ---------------------------------------------------------------------------
// Kernel 0: combined linear weights (layers are purely linear: no activation).
// Wc = W1 @ W2 @ W3 ; bc = (b1 @ W2 + b2) @ W3 + b3.  One block, 128 threads.
// ---------------------------------------------------------------------------
__global__ void precompute_kernel(const float* __restrict__ W1, const float* __restrict__ b1,
                                  const float* __restrict__ W2, const float* __restrict__ b2,
                                  const float* __restrict__ W3, const float* __restrict__ b3) {
    __shared__ float sW2[HID * HID];
    __shared__ float sW3[HID * CLS];
    const int t = threadIdx.x;
    for (int i = t; i < HID * HID; i += 128) sW2[i] = W2[i];
    for (int i = t; i < HID * CLS; i += 128) sW3[i] = W3[i];
    __syncthreads();

    // thread k computes row k of Wc
    float v[HID];
#pragma unroll
    for (int j = 0; j < HID; j++) v[j] = 0.f;
#pragma unroll
    for (int p = 0; p < HID; p++) {
        const float w = W1[t * HID + p];
#pragma unroll
        for (int j = 0; j < HID; j++) v[j] = fmaf(w, sW2[p * HID + j], v[j]);
    }
    float w[CLS];
#pragma unroll
    for (int j = 0; j < CLS; j++) w[j] = 0.f;
#pragma unroll
    for (int p = 0; p < HID; p++) {
#pragma unroll
        for (int j = 0; j < CLS; j++) w[j] = fmaf(v[p], sW3[p * CLS + j], w[j]);
    }
#pragma unroll
    for (int j = 0; j < CLS; j++) g_Wc[t * CLS + j] = w[j];

    if (t == 0) {
        float u[HID];
#pragma unroll
        for (int j = 0; j < HID; j++) u[j] = b2[j];
#pragma unroll
        for (int p = 0; p < HID; p++)
#pragma unroll
            for (int j = 0; j < HID; j++) u[j] = fmaf(b1[p], sW2[p * HID + j], u[j]);
        float bb[CLS];
#pragma unroll
        for (int j = 0; j < CLS; j++) bb[j] = b3[j];
#pragma unroll
        for (int p = 0; p < HID; p++)
#pragma unroll
            for (int j = 0; j < CLS; j++) bb[j] = fmaf(u[p], sW3[p * CLS + j], bb[j]);
#pragma unroll
        for (int j = 0; j < CLS; j++) g_bc[j] = bb[j];
    }
}

// ---------------------------------------------------------------------------
// Kernel 1: h = x @ Wc + bc -> g_Hs = fp16(h * sqrt(log2e)).
// One thread per (row, class). ALSO zeroes the atomic accumulators g_num/g_den.
// ---------------------------------------------------------------------------
__global__ __launch_bounds__(256)
void mlp_gemm(const float* __restrict__ x) {
    __shared__ float sWc[DIM * CLS];   // 8 KB
    __shared__ float sbc[CLS];

    const int tid = threadIdx.x;
    const int gid = blockIdx.x * 256 + tid;
    g_num[gid] = 0.f;
    if (gid < NN) g_den[gid] = 0.f;
    {
        const float4* src = reinterpret_cast<const float4*>(g_Wc);
        float4* dst = reinterpret_cast<float4*>(sWc);
        dst[tid]       = src[tid];
        dst[tid + 256] = src[tid + 256];
        if (tid < CLS) sbc[tid] = g_bc[tid];
    }
    __syncthreads();

    const int row = blockIdx.x * 16 + (tid >> 4);
    const int j   = tid & 15;

    const float4* xr = reinterpret_cast<const float4*>(x + (size_t)row * DIM);
    float a0 = 0.f, a1 = 0.f, a2 = 0.f, a3 = 0.f;
#pragma unroll
    for (int k4 = 0; k4 < 32; k4++) {
        const float4 xv = __ldg(&xr[k4]);
        a0 = fmaf(xv.x, sWc[(4 * k4 + 0) * CLS + j], a0);
        a1 = fmaf(xv.y, sWc[(4 * k4 + 1) * CLS + j], a1);
        a2 = fmaf(xv.z, sWc[(4 * k4 + 2) * CLS + j], a2);
        a3 = fmaf(xv.w, sWc[(4 * k4 + 3) * CLS + j], a3);
    }
    const float h = (a0 + a1) + (a2 + a3) + sbc[j];

    g_Hs[(size_t)row * HID + j] = __float2half(h * SQRT_LOG2E);
}

// ---------------------------------------------------------------------------
// Kernel 2: fused masked-softmax aggregation on tensor cores (fp16).
// Single smem layout (natural); the O-mma B-fragments are produced from the
// S-mma B-fragments via movmatrix.m8n8.trans — no transposed smem array, no
// transposition staging, fewer LSU ops in the mainloop.
// ---------------------------------------------------------------------------
__global__ __launch_bounds__(256, 4)
void agg_kernel() {
    __shared__ __align__(16) __half sHn[CHUNK * S_N];  // Hs[j][hid]  (24.0 KB)

    const int tid  = threadIdx.x;
    const int lane = tid & 31;
    const int wid  = tid >> 5;        // 0..7
    const int g    = lane >> 2;       // 0..7
    const int t4   = lane & 3;        // 0..3

    const int split = blockIdx.y;
    const int rbase = blockIdx.x * ROWS_CTA + wid * 16;
    const int rg  = rbase + g;
    const int rg8 = rg + 8;

    // A-fragment: scaled rows (loop-invariant)
    uint32_t a0 = *reinterpret_cast<const uint32_t*>(g_Hs + (size_t)rg  * HID + 2 * t4);
    uint32_t a1 = *reinterpret_cast<const uint32_t*>(g_Hs + (size_t)rg8 * HID + 2 * t4);
    uint32_t a2 = *reinterpret_cast<const uint32_t*>(g_Hs + (size_t)rg  * HID + 2 * t4 + 8);
    uint32_t a3 = *reinterpret_cast<const uint32_t*>(g_Hs + (size_t)rg8 * HID + 2 * t4 + 8);

    float o00 = 0.f, o01 = 0.f, o02 = 0.f, o03 = 0.f;
    float o10 = 0.f, o11 = 0.f, o12 = 0.f, o13 = 0.f;
    __half2 dga = __half2(__ushort_as_half(0), __ushort_as_half(0));
    __half2 dgb = dga;

    const int j0 = split * COLS_PS;

    for (int cc = 0; cc < COLS_PS; cc += CHUNK) {
        __syncthreads();
        // Stage (natural layout only): thread owns columns tid, tid+256.
#pragma unroll
        for (int it = 0; it < CHUNK / 256; it++) {
            const int j = tid + it * 256;
            const size_t gidx = (size_t)(j0 + cc + j) * HID;
            *reinterpret_cast<uint4*>(&sHn[j * S_N])     = *reinterpret_cast<const uint4*>(g_Hs + gidx);
            *reinterpret_cast<uint4*>(&sHn[j * S_N + 8]) = *reinterpret_cast<const uint4*>(g_Hs + gidx + 8);
        }
        __syncthreads();

#pragma unroll 16
        for (int kc = 0; kc < CHUNK / 16; kc++) {
            const int ja = 16 * kc + g;
            const int jb = ja + 8;
            uint32_t b0a = *reinterpret_cast<const uint32_t*>(&sHn[ja * S_N + 2 * t4]);
            uint32_t b1a = *reinterpret_cast<const uint32_t*>(&sHn[ja * S_N + 2 * t4 + 8]);
            uint32_t b0b = *reinterpret_cast<const uint32_t*>(&sHn[jb * S_N + 2 * t4]);
            uint32_t b1b = *reinterpret_cast<const uint32_t*>(&sHn[jb * S_N + 2 * t4 + 8]);

            // O-mma B fragments = 8x8 transposes of the S-mma B fragments
            uint32_t q0n0 = movm_t(b0a);   // Hs[16kc+2t4..][hid=g]
            uint32_t q1n0 = movm_t(b0b);   // Hs[16kc+8+2t4..][hid=g]
            uint32_t q0n1 = movm_t(b1a);   // Hs[16kc+2t4..][hid=g+8]
            uint32_t q1n1 = movm_t(b1b);   // Hs[16kc+8+2t4..][hid=g+8]

            // S-mma with fp16 accumulators: D-fragment IS the packed pair layout
            uint32_t c0a = 0u, c1a = 0u, c0b = 0u, c1b = 0u;
            mma_f16acc(c0a, c1a, a0, a1, a2, a3, b0a, b1a);
            mma_f16acc(c0b, c1b, a0, a1, a2, a3, b0b, b1b);

            uint32_t pa0 = masked_exp2h(c0a);
            uint32_t pa1 = masked_exp2h(c1a);
            uint32_t pa2 = masked_exp2h(c0b);
            uint32_t pa3 = masked_exp2h(c1b);

            dga = __hadd2(dga, __hadd2(u2h(pa0), u2h(pa2)));
            dgb = __hadd2(dgb, __hadd2(u2h(pa1), u2h(pa3)));

            mma_f16(o00, o01, o02, o03, pa0, pa1, pa2, pa3, q0n0, q1n0);
            mma_f16(o10, o11, o12, o13, pa0, pa1, pa2, pa3, q0n1, q1n1);
        }
    }

    // den: unpack, reduce across the 4 lanes sharing each row
    float den_g  = __half2float(dga.x) + __half2float(dga.y);
    float den_g8 = __half2float(dgb.x) + __half2float(dgb.y);
    den_g  += __shfl_xor_sync(0xffffffffu, den_g, 1);
    den_g  += __shfl_xor_sync(0xffffffffu, den_g, 2);
    den_g8 += __shfl_xor_sync(0xffffffffu, den_g8, 1);
    den_g8 += __shfl_xor_sync(0xffffffffu, den_g8, 2);

    // epilogue: atomic accumulation (spread addresses; 6 colliders each)
    float* pn  = g_num + (size_t)rg  * CLS;
    float* pn8 = g_num + (size_t)rg8 * CLS;
    atomicAdd(&pn [2 * t4],     o00);  atomicAdd(&pn [2 * t4 + 1], o01);
    atomicAdd(&pn [2 * t4 + 8], o10);  atomicAdd(&pn [2 * t4 + 9], o11);
    atomicAdd(&pn8[2 * t4],     o02);  atomicAdd(&pn8[2 * t4 + 1], o03);
    atomicAdd(&pn8[2 * t4 + 8], o12);  atomicAdd(&pn8[2 * t4 + 9], o13);
    if (t4 == 0) {
        atomicAdd(&g_den[rg],  den_g);
        atomicAdd(&g_den[rg8], den_g8);
    }
}

// ---------------------------------------------------------------------------
// Kernel 3: out = num/(den*sqrt(log2e)), then row log-softmax.
// Single-pass gather; 16 threads per row.
// ---------------------------------------------------------------------------
__global__ __launch_bounds__(256)
void finalize_kernel(float* __restrict__ out) {
    const int idx = blockIdx.x * 256 + threadIdx.x;
    const int row = idx >> 4;
    const int c   = idx & 15;

    const float n   = g_num[(size_t)row * CLS + c];
    const float den = g_den[row];

    const float o = n / (den * SQRT_LOG2E);

    float m = o;
    m = fmaxf(m, __shfl_xor_sync(0xffffffffu, m, 1));
    m = fmaxf(m, __shfl_xor_sync(0xffffffffu, m, 2));
    m = fmaxf(m, __shfl_xor_sync(0xffffffffu, m, 4));
    m = fmaxf(m, __shfl_xor_sync(0xffffffffu, m, 8));

    float sum = expf(o - m);
    sum += __shfl_xor_sync(0xffffffffu, sum, 1);
    sum += __shfl_xor_sync(0xffffffffu, sum, 2);
    sum += __shfl_xor_sync(0xffffffffu, sum, 4);
    sum += __shfl_xor_sync(0xffffffffu, sum, 8);

    out[(size_t)row * CLS + c] = o - (logf(sum) + m);
}

// ---------------------------------------------------------------------------
extern "C" void kernel_launch(void* const* d_in, const int* in_sizes, int n_in,
                              void* d_out, int out_size) {
    const float* x  = (const float*)d_in[0];
    const float* W1 = (const float*)d_in[1];
    const float* b1 = (const float*)d_in[2];
    const float* W2 = (const float*)d_in[3];
    const float* b2 = (const float*)d_in[4];
    const float* W3 = (const float*)d_in[5];
    const float* b3 = (const float*)d_in[6];
    float* out = (float*)d_out;

    precompute_kernel<<<1, 128>>>(W1, b1, W2, b2, W3, b3);
    mlp_gemm<<<NN / 16, 256>>>(x);

    dim3 grid(NN / ROWS_CTA, NSPLIT);
    agg_kernel<<<grid, 256>>>();

    finalize_kernel<<<(NN * 16) / 256, 256>>>(out);
}